// round 5
// baseline (speedup 1.0000x reference)
#include <cuda_runtime.h>
#include <cuda_bf16.h>
#include <cstdint>

#define T 256
#define Bt 64
#define EMB 300
#define HID 256
#define G4 1024
#define NLAB 20

typedef unsigned long long ull;

// ---------------- scratch ----------------
__device__ float g_xproj[2][T][G4][Bt];   // [dir][t][gate][batch]
__device__ float g_h[2][T][HID][Bt];      // [dir][t][hid][batch]
__device__ float g_em[T][Bt][NLAB];
__device__ float g_part[Bt];
__device__ unsigned g_flags[128];
__device__ unsigned g_rel;

// ---------------- f32x2 packed FMA (Blackwell) ----------------
__device__ __forceinline__ ull ffma2(ull a, ull b, ull c) {
    ull d;
    asm("fma.rn.f32x2 %0, %1, %2, %3;" : "=l"(d) : "l"(a), "l"(b), "l"(c));
    return d;
}
__device__ __forceinline__ float lo_hi_sum(ull v) {
    float2 f = *(float2*)&v;
    return f.x + f.y;
}

// ---------------- smem helpers ----------------
__device__ __forceinline__ uint32_t smem_u32(const void* p) {
    uint32_t a;
    asm("{ .reg .u64 t; cvta.to.shared.u64 t, %1; cvt.u32.u64 %0, t; }" : "=r"(a) : "l"(p));
    return a;
}
__device__ __forceinline__ void mbar_init(uint32_t mbar, uint32_t cnt) {
    asm volatile("mbarrier.init.shared.b64 [%0], %1;" :: "r"(mbar), "r"(cnt) : "memory");
}
__device__ __forceinline__ void mbar_expect_tx(uint32_t mbar, uint32_t bytes) {
    asm volatile("mbarrier.arrive.expect_tx.shared.b64 _, [%0], %1;" :: "r"(mbar), "r"(bytes) : "memory");
}
__device__ __forceinline__ void mbar_wait(uint32_t mbar, uint32_t phase) {
    asm volatile(
        "{\n\t.reg .pred P;\n"
        "WL_%=:\n\t"
        "mbarrier.try_wait.parity.shared.b64 P, [%0], %1;\n\t"
        "@!P bra WL_%=;\n\t}"
        :: "r"(mbar), "r"(phase) : "memory");
}
__device__ __forceinline__ void bulk_cp(uint32_t dst_smem, const void* src, uint32_t bytes, uint32_t mbar) {
    asm volatile(
        "cp.async.bulk.shared::cluster.global.mbarrier::complete_tx::bytes [%0], [%1], %2, [%3];"
        :: "r"(dst_smem), "l"(src), "r"(bytes), "r"(mbar) : "memory");
}

// =============================================================================
// Kernel 1: x_proj GEMM with K-paired f32x2 FMAs.
// Tiles: 64(m=batch of one t) x 64(gates) x 32(k). Smem layout: row-major
// [row][32k] with float4 slots XOR-swizzled by (row&7) -> conflict-free LDS.128.
// Thread (tx,ty) computes rows {tx+16i} x cols {ty+16j}.
// =============================================================================
__device__ __forceinline__ int swz(int row, int kk) {
    return row * 32 + ((((kk >> 2) ^ (row & 7)) << 2) | (kk & 3));
}

__global__ void __launch_bounds__(256) k_xproj(
    const float* __restrict__ emb,
    const float* __restrict__ Wf, const float* __restrict__ bf,
    const float* __restrict__ Wb, const float* __restrict__ bb,
    const int*   __restrict__ sent)
{
    __shared__ float As[64 * 32];
    __shared__ float Bs[64 * 32];
    __shared__ int   ws[64];

    int t   = blockIdx.y;
    int n0  = blockIdx.x * 64;
    int dir = (n0 >= 1024) ? 1 : 0;
    const float* W    = dir ? Wb : Wf;
    const float* bias = dir ? bb : bf;
    int gbase = n0 & 1023;
    int tid = threadIdx.x;

    if (tid < 64) ws[tid] = sent[t * 64 + tid];
    __syncthreads();

    ull acc[4][4];
    #pragma unroll
    for (int i = 0; i < 4; i++)
        #pragma unroll
        for (int j = 0; j < 4; j++) acc[i][j] = 0ull;

    int tx = tid & 15;
    int ty = tid >> 4;
    int sa = tx & 7;   // swizzle key for A rows (row&7 == tx&7 since rows = tx+16i)
    int sb = ty & 7;

    for (int kt = 0; kt < 10; kt++) {
        int k0 = kt * 32;
        #pragma unroll
        for (int i = 0; i < 8; i++) {
            int idx = tid + i * 256;
            int m  = idx >> 5;
            int kk = idx & 31;
            int kg = k0 + kk;
            float av = 0.f, bv = 0.f;
            if (kg < EMB) {
                av = emb[ws[m] * EMB + kg];
                bv = W[(gbase + m) * EMB + kg];
            }
            As[swz(m, kk)] = av;
            Bs[swz(m, kk)] = bv;
        }
        __syncthreads();

        #pragma unroll
        for (int c = 0; c < 8; c++) {
            ulonglong2 a[4], b[4];
            int ca = (c ^ sa) << 2;
            int cb = (c ^ sb) << 2;
            #pragma unroll
            for (int i = 0; i < 4; i++)
                a[i] = *(const ulonglong2*)&As[(tx + 16 * i) * 32 + ca];
            #pragma unroll
            for (int j = 0; j < 4; j++)
                b[j] = *(const ulonglong2*)&Bs[(ty + 16 * j) * 32 + cb];
            #pragma unroll
            for (int i = 0; i < 4; i++)
                #pragma unroll
                for (int j = 0; j < 4; j++) {
                    acc[i][j] = ffma2(a[i].x, b[j].x, acc[i][j]);
                    acc[i][j] = ffma2(a[i].y, b[j].y, acc[i][j]);
                }
        }
        __syncthreads();
    }

    #pragma unroll
    for (int j = 0; j < 4; j++) {
        int g = gbase + ty + 16 * j;
        float bv = bias[g];
        #pragma unroll
        for (int i = 0; i < 4; i++) {
            int m = tx + 16 * i;
            g_xproj[dir][t][g][m] = lo_hi_sum(acc[i][j]) + bv;
        }
    }
}

// =============================================================================
// Kernel 2: persistent bidirectional LSTM, 128 CTAs x 256 threads.
// CTA c owns hid cols [4c,4c+4); Whh slice duplicated as f32x2 in smem;
// h(t-1) streamed in via 4x chunked cp.async.bulk overlapped with the K-loop;
// flag-based grid barrier (no single-address atomic pileup).
// =============================================================================
__device__ __forceinline__ float sigf(float x) { return 1.f / (1.f + __expf(-x)); }

__device__ __forceinline__ void grid_barrier2(int bx, int tid, unsigned target)
{
    __threadfence();
    __syncthreads();
    if (tid == 0) ((volatile unsigned*)g_flags)[bx] = target;
    if (bx == 0) {
        if (tid < 32) {
            volatile unsigned* f = g_flags;
            for (;;) {
                bool ok = (f[tid] >= target) & (f[tid + 32] >= target)
                        & (f[tid + 64] >= target) & (f[tid + 96] >= target);
                if (__all_sync(0xffffffffu, ok)) break;
            }
            if (tid == 0) {
                __threadfence();
                *(volatile unsigned*)&g_rel = target;
            }
        }
    } else if (tid == 0) {
        volatile unsigned* r = &g_rel;
        while (*r < target) {}
    }
    __syncthreads();
    __threadfence();
}

#define LSTM_SMEM (32768 + 65536 + 4352 + 64)

__global__ void __launch_bounds__(256) k_lstm(
    const float* __restrict__ Whf, const float* __restrict__ Whb)
{
    extern __shared__ float sm[];
    ull*   Ws2 = (ull*)sm;                 // [k=256][16] duplicated pairs, 32KB
    float* hs  = sm + 8192;                // [k=256][b=64], 64KB
    float* gb  = sm + 8192 + 16384;        // [16][68]
    uint32_t mbar0 = smem_u32(sm + 8192 + 16384 + 1088);  // 4 mbarriers

    int bx  = blockIdx.x;
    int dir = bx >> 6;
    int cc  = bx & 63;
    const float* Whh = dir ? Whb : Whf;
    int tid = threadIdx.x;

    // preload duplicated Whh slice: Ws2[k*16 + r] = dup(Whh[q*256 + 4cc + j][k])
    for (int idx = tid; idx < 4096; idx += 256) {
        int k = idx & 255, r = idx >> 8;
        int q = r >> 2, j = r & 3;
        float w = Whh[(q * 256 + 4 * cc + j) * HID + k];
        float2 w2 = make_float2(w, w);
        Ws2[k * 16 + r] = *(ull*)&w2;
    }
    if (tid == 0)
        for (int ch = 0; ch < 4; ch++) mbar_init(mbar0 + ch * 8, 1);
    __syncthreads();

    int gi = tid & 15;       // gate col (q*4+j)
    int bg = tid >> 4;       // batch group of 4
    int q  = gi >> 2, jj = gi & 3;
    int jrow = tid >> 6;
    int bcol = tid & 63;
    float cstate = 0.f;

    float* hb = &g_h[dir][0][0][0];
    uint32_t hs_smem = smem_u32(hs);

    for (int step = 0; step < T; step++) {
        int t = dir ? (T - 1 - step) : step;

        if (step > 0 && tid == 0) {
            int tprev = dir ? (t + 1) : (t - 1);
            const float* src = hb + tprev * HID * Bt;
            #pragma unroll
            for (int ch = 0; ch < 4; ch++) {
                mbar_expect_tx(mbar0 + ch * 8, 16384);
                bulk_cp(hs_smem + ch * 16384, src + ch * 4096, 16384, mbar0 + ch * 8);
            }
        }

        // prefetch x_proj contribution
        float4 xp4 = *(const float4*)&g_xproj[dir][t][q * 256 + 4 * cc + jj][bg * 4];

        ull acc01 = 0ull, acc23 = 0ull;
        if (step > 0) {
            uint32_t phase = (unsigned)(step - 1) & 1u;
            #pragma unroll
            for (int ch = 0; ch < 4; ch++) {
                mbar_wait(mbar0 + ch * 8, phase);
                #pragma unroll 8
                for (int k = ch * 64; k < ch * 64 + 64; k++) {
                    ull w2 = Ws2[k * 16 + gi];
                    ulonglong2 h2 = *(const ulonglong2*)&hs[k * 64 + bg * 4];
                    acc01 = ffma2(w2, h2.x, acc01);
                    acc23 = ffma2(w2, h2.y, acc23);
                }
            }
        }
        float2 p01 = *(float2*)&acc01;
        float2 p23 = *(float2*)&acc23;
        *(float4*)&gb[gi * 68 + bg * 4] =
            make_float4(p01.x + xp4.x, p01.y + xp4.y, p23.x + xp4.z, p23.y + xp4.w);
        __syncthreads();

        float iv = gb[( 0 + jrow) * 68 + bcol];
        float fv = gb[( 4 + jrow) * 68 + bcol];
        float gv = gb[( 8 + jrow) * 68 + bcol];
        float ov = gb[(12 + jrow) * 68 + bcol];
        cstate = sigf(fv) * cstate + sigf(iv) * tanhf(gv);
        float hv = sigf(ov) * tanhf(cstate);
        hb[t * HID * Bt + (4 * cc + jrow) * Bt + bcol] = hv;

        grid_barrier2(bx, tid, (unsigned)(step + 1));
    }
}

// =============================================================================
// Kernel 3: emissions
// =============================================================================
__global__ void __launch_bounds__(256) k_emis(
    const float* __restrict__ Wt, const float* __restrict__ bt)
{
    extern __shared__ float sm[];
    float* Wts = sm;
    float* hch = sm + 10240;

    int t = blockIdx.x, tid = threadIdx.x;
    for (int i = tid; i < NLAB * 2 * HID; i += 256) Wts[i] = Wt[i];

    float acc[5] = {0.f, 0.f, 0.f, 0.f, 0.f};
    int b = tid & 63;
    int lbase = tid >> 6;

    for (int d = 0; d < 2; d++) {
        const float* hsrc = &g_h[d][t][0][0];
        for (int jc = 0; jc < 4; jc++) {
            __syncthreads();
            for (int i = tid; i < 4096; i += 256) hch[i] = hsrc[jc * 4096 + i];
            __syncthreads();
            #pragma unroll 4
            for (int j2 = 0; j2 < 64; j2++) {
                float hv = hch[j2 * 64 + b];
                #pragma unroll
                for (int s = 0; s < 5; s++) {
                    int l = lbase + 4 * s;
                    acc[s] += hv * Wts[l * 2 * HID + d * HID + jc * 64 + j2];
                }
            }
        }
    }
    #pragma unroll
    for (int s = 0; s < 5; s++) {
        int l = lbase + 4 * s;
        g_em[t][b][l] = acc[s] + bt[l];
    }
}

// =============================================================================
// Kernel 4: CRF per batch
// =============================================================================
__global__ void __launch_bounds__(64) k_crf(
    const int* __restrict__ sent, const int* __restrict__ labels,
    const float* __restrict__ start_t, const float* __restrict__ end_t,
    const float* __restrict__ trans)
{
    int b = blockIdx.x;
    int tid = threadIdx.x;
    __shared__ float s_score, s_denom;

    if (tid < 32) {
        int j = tid;
        float tcol[NLAB];
        #pragma unroll
        for (int i = 0; i < NLAB; i++) tcol[i] = (j < NLAB) ? trans[i * NLAB + j] : 0.f;
        float alpha = (j < NLAB) ? (start_t[j] + g_em[0][b][j]) : -1e30f;

        for (int t = 1; t < T; t++) {
            bool m = (sent[t * 64 + b] != 0);
            float em = (j < NLAB) ? g_em[t][b][j] : 0.f;
            float s[NLAB], mx = -1e30f;
            #pragma unroll
            for (int i = 0; i < NLAB; i++) {
                float ai = __shfl_sync(0xffffffffu, alpha, i);
                s[i] = ai + tcol[i];
                mx = fmaxf(mx, s[i]);
            }
            float sum = 0.f;
            #pragma unroll
            for (int i = 0; i < NLAB; i++) sum += __expf(s[i] - mx);
            float nxt = em + mx + __logf(sum);
            if (j < NLAB && m) alpha = nxt;
        }
        float v = (j < NLAB) ? (alpha + end_t[j]) : -1e30f;
        float mx = v;
        #pragma unroll
        for (int o = 16; o > 0; o >>= 1) mx = fmaxf(mx, __shfl_xor_sync(0xffffffffu, mx, o));
        float e = (j < NLAB) ? __expf(v - mx) : 0.f;
        #pragma unroll
        for (int o = 16; o > 0; o >>= 1) e += __shfl_xor_sync(0xffffffffu, e, o);
        if (tid == 0) s_denom = mx + __logf(e);
    } else {
        int l = tid - 32;
        float part = 0.f; int cnt = 0;
        for (int t = l; t < T; t += 32) {
            bool m = (sent[t * 64 + b] != 0);
            cnt += m ? 1 : 0;
            if (t >= 1 && m) {
                int tp = labels[(t - 1) * 64 + b];
                int tc = labels[t * 64 + b];
                part += trans[tp * NLAB + tc] + g_em[t][b][tc];
            }
        }
        #pragma unroll
        for (int o = 16; o > 0; o >>= 1) {
            part += __shfl_xor_sync(0xffffffffu, part, o);
            cnt  += __shfl_xor_sync(0xffffffffu, cnt, o);
        }
        if (l == 0) {
            int tag0 = labels[b];
            float score = start_t[tag0] + g_em[0][b][tag0] + part;
            int se = cnt - 1;
            int last = labels[se * 64 + b];
            score += end_t[last];
            s_score = score;
        }
    }
    __syncthreads();
    if (tid == 0) g_part[b] = s_denom - s_score;
}

__global__ void k_reduce(float* out)
{
    if (threadIdx.x == 0) {
        float s = 0.f;
        for (int b = 0; b < Bt; b++) s += g_part[b];
        out[0] = s;
    }
}

// =============================================================================
extern "C" void kernel_launch(void* const* d_in, const int* in_sizes, int n_in,
                              void* d_out, int out_size)
{
    const float* emb    = (const float*)d_in[0];
    const float* Wih_f  = (const float*)d_in[1];
    const float* Whh_f  = (const float*)d_in[2];
    const float* b_f    = (const float*)d_in[3];
    const float* Wih_b  = (const float*)d_in[4];
    const float* Whh_b  = (const float*)d_in[5];
    const float* b_b    = (const float*)d_in[6];
    const float* W_top  = (const float*)d_in[7];
    const float* b_top  = (const float*)d_in[8];
    const float* startt = (const float*)d_in[9];
    const float* endt   = (const float*)d_in[10];
    const float* trans  = (const float*)d_in[11];
    const int*   sent   = (const int*)d_in[12];
    const int*   labels = (const int*)d_in[13];
    float* out = (float*)d_out;

    cudaFuncSetAttribute(k_lstm, cudaFuncAttributeMaxDynamicSharedMemorySize, LSTM_SMEM);
    cudaFuncSetAttribute(k_emis, cudaFuncAttributeMaxDynamicSharedMemorySize, 57344);

    // reset barrier flags (captured in graph, runs each replay)
    void* fp = nullptr; void* rp = nullptr;
    cudaGetSymbolAddress(&fp, g_flags);
    cudaGetSymbolAddress(&rp, g_rel);
    cudaMemsetAsync(fp, 0, 128 * sizeof(unsigned));
    cudaMemsetAsync(rp, 0, sizeof(unsigned));

    k_xproj<<<dim3(32, 256), 256>>>(emb, Wih_f, b_f, Wih_b, b_b, sent);
    k_lstm <<<128, 256, LSTM_SMEM>>>(Whh_f, Whh_b);
    k_emis <<<256, 256, 57344>>>(W_top, b_top);
    k_crf  <<<64, 64>>>(sent, labels, startt, endt, trans);
    k_reduce<<<1, 32>>>(out);
}

// round 7
// speedup vs baseline: 1.1331x; 1.1331x over previous
#include <cuda_runtime.h>
#include <cuda_bf16.h>
#include <cstdint>

#define T 256
#define Bt 64
#define EMB 300
#define HID 256
#define G4 1024
#define NLAB 20

typedef unsigned long long ull;

// ---------------- scratch ----------------
__device__ float g_xproj[2][T][G4][Bt];   // [dir][t][gate][batch]
__device__ float g_h[2][T][HID][Bt];      // [dir][t][hid][batch]
__device__ float g_em[T][Bt][NLAB];
__device__ float g_part[Bt];
__device__ unsigned g_flags[128];
__device__ unsigned g_rel;

// ---------------- f32x2 packed FMA (Blackwell) ----------------
__device__ __forceinline__ ull ffma2(ull a, ull b, ull c) {
    ull d;
    asm("fma.rn.f32x2 %0, %1, %2, %3;" : "=l"(d) : "l"(a), "l"(b), "l"(c));
    return d;
}
__device__ __forceinline__ float lo_hi_sum(ull v) {
    float2 f = *(float2*)&v;
    return f.x + f.y;
}

// ---------------- smem / async helpers ----------------
__device__ __forceinline__ uint32_t smem_u32(const void* p) {
    uint32_t a;
    asm("{ .reg .u64 t; cvta.to.shared.u64 t, %1; cvt.u32.u64 %0, t; }" : "=r"(a) : "l"(p));
    return a;
}
__device__ __forceinline__ void mbar_init(uint32_t mbar, uint32_t cnt) {
    asm volatile("mbarrier.init.shared.b64 [%0], %1;" :: "r"(mbar), "r"(cnt) : "memory");
}
__device__ __forceinline__ void mbar_expect_tx(uint32_t mbar, uint32_t bytes) {
    asm volatile("mbarrier.arrive.expect_tx.shared.b64 _, [%0], %1;" :: "r"(mbar), "r"(bytes) : "memory");
}
__device__ __forceinline__ void mbar_wait(uint32_t mbar, uint32_t phase) {
    asm volatile(
        "{\n\t.reg .pred P;\n"
        "WL_%=:\n\t"
        "mbarrier.try_wait.parity.shared.b64 P, [%0], %1;\n\t"
        "@!P bra WL_%=;\n\t}"
        :: "r"(mbar), "r"(phase) : "memory");
}
__device__ __forceinline__ void bulk_cp(uint32_t dst_smem, const void* src, uint32_t bytes, uint32_t mbar) {
    asm volatile(
        "cp.async.bulk.shared::cluster.global.mbarrier::complete_tx::bytes [%0], [%1], %2, [%3];"
        :: "r"(dst_smem), "l"(src), "r"(bytes), "r"(mbar) : "memory");
}
__device__ __forceinline__ void cp_async16(uint32_t dst, const void* src, uint32_t srcbytes) {
    asm volatile("cp.async.ca.shared.global [%0], [%1], 16, %2;"
                 :: "r"(dst), "l"(src), "r"(srcbytes) : "memory");
}
#define CP_COMMIT() asm volatile("cp.async.commit_group;" ::: "memory")
#define CP_WAIT1()  asm volatile("cp.async.wait_group 1;" ::: "memory")
#define CP_WAIT0()  asm volatile("cp.async.wait_group 0;" ::: "memory")

// =============================================================================
// Kernel 1: x_proj GEMM, 2-stage cp.async double-buffered, f32x2 K-paired FMAs.
// Tile 64(m) x 64(g) x 32(k). Smem [row][32k] row-major, float4 slots XOR-
// swizzled by (row&7). Thread (tx,ty) -> rows {tx+16i}, cols {ty+16j}.
// =============================================================================
__global__ void __launch_bounds__(256) k_xproj(
    const float* __restrict__ emb,
    const float* __restrict__ Wf, const float* __restrict__ bf,
    const float* __restrict__ Wb, const float* __restrict__ bb,
    const int*   __restrict__ sent)
{
    __shared__ float As[2][64 * 32];
    __shared__ float Bs[2][64 * 32];
    __shared__ int   ws[64];

    int t   = blockIdx.y;
    int n0  = blockIdx.x * 64;
    int dir = (n0 >= 1024) ? 1 : 0;
    const float* W    = dir ? Wb : Wf;
    const float* bias = dir ? bb : bf;
    int gbase = n0 & 1023;
    int tid = threadIdx.x;

    if (tid < 64) ws[tid] = sent[t * 64 + tid];
    __syncthreads();

    uint32_t as_base = smem_u32(&As[0][0]);
    uint32_t bs_base = smem_u32(&Bs[0][0]);

    // per-thread load slots: s = tid + 256*i, i=0..1 ; row = s>>3, slot = s&7
    int r0 = tid >> 3,          sl0 = tid & 7;
    int r1 = (tid + 256) >> 3,  sl1 = (tid + 256) & 7;
    uint32_t d0 = (uint32_t)(r0 * 128 + ((sl0 ^ (r0 & 7)) << 4));
    uint32_t d1 = (uint32_t)(r1 * 128 + ((sl1 ^ (r1 & 7)) << 4));
    const float* arow0 = emb + (size_t)ws[r0] * EMB;
    const float* arow1 = emb + (size_t)ws[r1] * EMB;
    const float* brow0 = W + (size_t)(gbase + r0) * EMB;
    const float* brow1 = W + (size_t)(gbase + r1) * EMB;

    auto issue = [&](int kt, int buf) {
        int k0 = kt * 32;
        uint32_t boff = (uint32_t)(buf * 8192);  // 2048 floats
        int kg0 = k0 + sl0 * 4, kg1 = k0 + sl1 * 4;
        uint32_t n0b = (kg0 + 4 <= EMB) ? 16u : 0u;
        uint32_t n1b = (kg1 + 4 <= EMB) ? 16u : 0u;
        cp_async16(as_base + boff + d0, arow0 + (n0b ? kg0 : 0), n0b);
        cp_async16(as_base + boff + d1, arow1 + (n1b ? kg1 : 0), n1b);
        cp_async16(bs_base + boff + d0, brow0 + (n0b ? kg0 : 0), n0b);
        cp_async16(bs_base + boff + d1, brow1 + (n1b ? kg1 : 0), n1b);
    };

    ull acc[4][4];
    #pragma unroll
    for (int i = 0; i < 4; i++)
        #pragma unroll
        for (int j = 0; j < 4; j++) acc[i][j] = 0ull;

    int tx = tid & 15;
    int ty = tid >> 4;
    int sa = tx & 7;
    int sb = ty & 7;

    issue(0, 0);
    CP_COMMIT();

    for (int kt = 0; kt < 10; kt++) {
        if (kt < 9) {
            issue(kt + 1, (kt + 1) & 1);
            CP_COMMIT();
            CP_WAIT1();
        } else {
            CP_WAIT0();
        }
        __syncthreads();

        const float* Ab = &As[kt & 1][0];
        const float* Bb = &Bs[kt & 1][0];
        #pragma unroll
        for (int c = 0; c < 8; c++) {
            ulonglong2 a[4], b[4];
            int ca = (c ^ sa) << 2;
            int cb = (c ^ sb) << 2;
            #pragma unroll
            for (int i = 0; i < 4; i++)
                a[i] = *(const ulonglong2*)&Ab[(tx + 16 * i) * 32 + ca];
            #pragma unroll
            for (int j = 0; j < 4; j++)
                b[j] = *(const ulonglong2*)&Bb[(ty + 16 * j) * 32 + cb];
            #pragma unroll
            for (int i = 0; i < 4; i++)
                #pragma unroll
                for (int j = 0; j < 4; j++) {
                    acc[i][j] = ffma2(a[i].x, b[j].x, acc[i][j]);
                    acc[i][j] = ffma2(a[i].y, b[j].y, acc[i][j]);
                }
        }
        __syncthreads();
    }

    #pragma unroll
    for (int j = 0; j < 4; j++) {
        int g = gbase + ty + 16 * j;
        float bv = bias[g];
        #pragma unroll
        for (int i = 0; i < 4; i++) {
            int m = tx + 16 * i;
            g_xproj[dir][t][g][m] = lo_hi_sum(acc[i][j]) + bv;
        }
    }
}

// =============================================================================
// Kernel 2: persistent bidirectional LSTM (UNCHANGED from R4 — profiled this
// round at launch position 6).
// =============================================================================
__device__ __forceinline__ float sigf(float x) { return 1.f / (1.f + __expf(-x)); }

__device__ __forceinline__ void grid_barrier2(int bx, int tid, unsigned target)
{
    __threadfence();
    __syncthreads();
    if (tid == 0) ((volatile unsigned*)g_flags)[bx] = target;
    if (bx == 0) {
        if (tid < 32) {
            volatile unsigned* f = g_flags;
            for (;;) {
                bool ok = (f[tid] >= target) & (f[tid + 32] >= target)
                        & (f[tid + 64] >= target) & (f[tid + 96] >= target);
                if (__all_sync(0xffffffffu, ok)) break;
            }
            if (tid == 0) {
                __threadfence();
                *(volatile unsigned*)&g_rel = target;
            }
        }
    } else if (tid == 0) {
        volatile unsigned* r = &g_rel;
        while (*r < target) {}
    }
    __syncthreads();
    __threadfence();
}

#define LSTM_SMEM (32768 + 65536 + 4352 + 64)

__global__ void __launch_bounds__(256) k_lstm(
    const float* __restrict__ Whf, const float* __restrict__ Whb)
{
    extern __shared__ float sm[];
    ull*   Ws2 = (ull*)sm;                 // [k=256][16] duplicated pairs, 32KB
    float* hs  = sm + 8192;                // [k=256][b=64], 64KB
    float* gb  = sm + 8192 + 16384;        // [16][68]
    uint32_t mbar0 = smem_u32(sm + 8192 + 16384 + 1088);  // 4 mbarriers

    int bx  = blockIdx.x;
    int dir = bx >> 6;
    int cc  = bx & 63;
    const float* Whh = dir ? Whb : Whf;
    int tid = threadIdx.x;

    for (int idx = tid; idx < 4096; idx += 256) {
        int k = idx & 255, r = idx >> 8;
        int q = r >> 2, j = r & 3;
        float w = Whh[(q * 256 + 4 * cc + j) * HID + k];
        float2 w2 = make_float2(w, w);
        Ws2[k * 16 + r] = *(ull*)&w2;
    }
    if (tid == 0)
        for (int ch = 0; ch < 4; ch++) mbar_init(mbar0 + ch * 8, 1);
    __syncthreads();

    int gi = tid & 15;
    int bg = tid >> 4;
    int q  = gi >> 2, jj = gi & 3;
    int jrow = tid >> 6;
    int bcol = tid & 63;
    float cstate = 0.f;

    float* hb = &g_h[dir][0][0][0];
    uint32_t hs_smem = smem_u32(hs);

    for (int step = 0; step < T; step++) {
        int t = dir ? (T - 1 - step) : step;

        if (step > 0 && tid == 0) {
            int tprev = dir ? (t + 1) : (t - 1);
            const float* src = hb + tprev * HID * Bt;
            #pragma unroll
            for (int ch = 0; ch < 4; ch++) {
                mbar_expect_tx(mbar0 + ch * 8, 16384);
                bulk_cp(hs_smem + ch * 16384, src + ch * 4096, 16384, mbar0 + ch * 8);
            }
        }

        float4 xp4 = *(const float4*)&g_xproj[dir][t][q * 256 + 4 * cc + jj][bg * 4];

        ull acc01 = 0ull, acc23 = 0ull;
        if (step > 0) {
            uint32_t phase = (unsigned)(step - 1) & 1u;
            #pragma unroll
            for (int ch = 0; ch < 4; ch++) {
                mbar_wait(mbar0 + ch * 8, phase);
                #pragma unroll 8
                for (int k = ch * 64; k < ch * 64 + 64; k++) {
                    ull w2 = Ws2[k * 16 + gi];
                    ulonglong2 h2 = *(const ulonglong2*)&hs[k * 64 + bg * 4];
                    acc01 = ffma2(w2, h2.x, acc01);
                    acc23 = ffma2(w2, h2.y, acc23);
                }
            }
        }
        float2 p01 = *(float2*)&acc01;
        float2 p23 = *(float2*)&acc23;
        *(float4*)&gb[gi * 68 + bg * 4] =
            make_float4(p01.x + xp4.x, p01.y + xp4.y, p23.x + xp4.z, p23.y + xp4.w);
        __syncthreads();

        float iv = gb[( 0 + jrow) * 68 + bcol];
        float fv = gb[( 4 + jrow) * 68 + bcol];
        float gv = gb[( 8 + jrow) * 68 + bcol];
        float ov = gb[(12 + jrow) * 68 + bcol];
        cstate = sigf(fv) * cstate + sigf(iv) * tanhf(gv);
        float hv = sigf(ov) * tanhf(cstate);
        hb[t * HID * Bt + (4 * cc + jrow) * Bt + bcol] = hv;

        grid_barrier2(bx, tid, (unsigned)(step + 1));
    }
}

// =============================================================================
// Kernel 3: emissions
// =============================================================================
__global__ void __launch_bounds__(256) k_emis(
    const float* __restrict__ Wt, const float* __restrict__ bt)
{
    extern __shared__ float sm[];
    float* Wts = sm;
    float* hch = sm + 10240;

    int t = blockIdx.x, tid = threadIdx.x;
    for (int i = tid; i < NLAB * 2 * HID; i += 256) Wts[i] = Wt[i];

    float acc[5] = {0.f, 0.f, 0.f, 0.f, 0.f};
    int b = tid & 63;
    int lbase = tid >> 6;

    for (int d = 0; d < 2; d++) {
        const float* hsrc = &g_h[d][t][0][0];
        for (int jc = 0; jc < 4; jc++) {
            __syncthreads();
            for (int i = tid; i < 4096; i += 256) hch[i] = hsrc[jc * 4096 + i];
            __syncthreads();
            #pragma unroll 4
            for (int j2 = 0; j2 < 64; j2++) {
                float hv = hch[j2 * 64 + b];
                #pragma unroll
                for (int s = 0; s < 5; s++) {
                    int l = lbase + 4 * s;
                    acc[s] += hv * Wts[l * 2 * HID + d * HID + jc * 64 + j2];
                }
            }
        }
    }
    #pragma unroll
    for (int s = 0; s < 5; s++) {
        int l = lbase + 4 * s;
        g_em[t][b][l] = acc[s] + bt[l];
    }
}

// =============================================================================
// Kernel 4: CRF per batch
// =============================================================================
__global__ void __launch_bounds__(64) k_crf(
    const int* __restrict__ sent, const int* __restrict__ labels,
    const float* __restrict__ start_t, const float* __restrict__ end_t,
    const float* __restrict__ trans)
{
    int b = blockIdx.x;
    int tid = threadIdx.x;
    __shared__ float s_score, s_denom;

    if (tid < 32) {
        int j = tid;
        float tcol[NLAB];
        #pragma unroll
        for (int i = 0; i < NLAB; i++) tcol[i] = (j < NLAB) ? trans[i * NLAB + j] : 0.f;
        float alpha = (j < NLAB) ? (start_t[j] + g_em[0][b][j]) : -1e30f;

        for (int t = 1; t < T; t++) {
            bool m = (sent[t * 64 + b] != 0);
            float em = (j < NLAB) ? g_em[t][b][j] : 0.f;
            float s[NLAB], mx = -1e30f;
            #pragma unroll
            for (int i = 0; i < NLAB; i++) {
                float ai = __shfl_sync(0xffffffffu, alpha, i);
                s[i] = ai + tcol[i];
                mx = fmaxf(mx, s[i]);
            }
            float sum = 0.f;
            #pragma unroll
            for (int i = 0; i < NLAB; i++) sum += __expf(s[i] - mx);
            float nxt = em + mx + __logf(sum);
            if (j < NLAB && m) alpha = nxt;
        }
        float v = (j < NLAB) ? (alpha + end_t[j]) : -1e30f;
        float mx = v;
        #pragma unroll
        for (int o = 16; o > 0; o >>= 1) mx = fmaxf(mx, __shfl_xor_sync(0xffffffffu, mx, o));
        float e = (j < NLAB) ? __expf(v - mx) : 0.f;
        #pragma unroll
        for (int o = 16; o > 0; o >>= 1) e += __shfl_xor_sync(0xffffffffu, e, o);
        if (tid == 0) s_denom = mx + __logf(e);
    } else {
        int l = tid - 32;
        float part = 0.f; int cnt = 0;
        for (int t = l; t < T; t += 32) {
            bool m = (sent[t * 64 + b] != 0);
            cnt += m ? 1 : 0;
            if (t >= 1 && m) {
                int tp = labels[(t - 1) * 64 + b];
                int tc = labels[t * 64 + b];
                part += trans[tp * NLAB + tc] + g_em[t][b][tc];
            }
        }
        #pragma unroll
        for (int o = 16; o > 0; o >>= 1) {
            part += __shfl_xor_sync(0xffffffffu, part, o);
            cnt  += __shfl_xor_sync(0xffffffffu, cnt, o);
        }
        if (l == 0) {
            int tag0 = labels[b];
            float score = start_t[tag0] + g_em[0][b][tag0] + part;
            int se = cnt - 1;
            int last = labels[se * 64 + b];
            score += end_t[last];
            s_score = score;
        }
    }
    __syncthreads();
    if (tid == 0) g_part[b] = s_denom - s_score;
}

__global__ void k_reduce(float* out)
{
    if (threadIdx.x == 0) {
        float s = 0.f;
        for (int b = 0; b < Bt; b++) s += g_part[b];
        out[0] = s;
    }
}

// ---- barrier reset + no-op padding so ncu (-s 5 -c 1) captures k_lstm ------
__global__ void k_reset()
{
    int i = threadIdx.x;
    if (i < 128) g_flags[i] = 0u;
    if (i == 0)  g_rel = 0u;
}
__global__ void k_nop() {}

// =============================================================================
extern "C" void kernel_launch(void* const* d_in, const int* in_sizes, int n_in,
                              void* d_out, int out_size)
{
    const float* emb    = (const float*)d_in[0];
    const float* Wih_f  = (const float*)d_in[1];
    const float* Whh_f  = (const float*)d_in[2];
    const float* b_f    = (const float*)d_in[3];
    const float* Wih_b  = (const float*)d_in[4];
    const float* Whh_b  = (const float*)d_in[5];
    const float* b_b    = (const float*)d_in[6];
    const float* W_top  = (const float*)d_in[7];
    const float* b_top  = (const float*)d_in[8];
    const float* startt = (const float*)d_in[9];
    const float* endt   = (const float*)d_in[10];
    const float* trans  = (const float*)d_in[11];
    const int*   sent   = (const int*)d_in[12];
    const int*   labels = (const int*)d_in[13];
    float* out = (float*)d_out;

    cudaFuncSetAttribute(k_lstm, cudaFuncAttributeMaxDynamicSharedMemorySize, LSTM_SMEM);
    cudaFuncSetAttribute(k_emis, cudaFuncAttributeMaxDynamicSharedMemorySize, 57344);

    // Launch positions (ncu: -s 5 -c 1 -> captures #6 = k_lstm):
    // 1:k_reset 2:k_nop 3:k_nop 4:k_nop 5:k_xproj 6:k_lstm 7:k_emis 8:k_crf 9:k_reduce
    k_reset<<<1, 128>>>();
    k_nop<<<1, 32>>>();
    k_nop<<<1, 32>>>();
    k_nop<<<1, 32>>>();
    k_xproj<<<dim3(32, 256), 256>>>(emb, Wih_f, b_f, Wih_b, b_b, sent);
    k_lstm <<<128, 256, LSTM_SMEM>>>(Whh_f, Whh_b);
    k_emis <<<256, 256, 57344>>>(W_top, b_top);
    k_crf  <<<64, 64>>>(sent, labels, startt, endt, trans);
    k_reduce<<<1, 32>>>(out);
}

// round 9
// speedup vs baseline: 1.5348x; 1.3545x over previous
#include <cuda_runtime.h>
#include <cuda_bf16.h>
#include <cstdint>

#define T 256
#define Bt 64
#define EMB 300
#define HID 256
#define G4 1024
#define NLAB 20

typedef unsigned long long ull;

// ---------------- scratch ----------------
__device__ float g_xproj[2][T][G4][Bt];   // [dir][t][gate][batch]
__device__ float g_h[2][T][HID][Bt];      // [dir][t][hid][batch]
__device__ float g_em[T][Bt][NLAB];
__device__ float g_part[Bt];
__device__ unsigned g_flags[128];
__device__ unsigned g_rel;

// ---------------- f32x2 packed FMA (Blackwell) ----------------
__device__ __forceinline__ ull ffma2(ull a, ull b, ull c) {
    ull d;
    asm("fma.rn.f32x2 %0, %1, %2, %3;" : "=l"(d) : "l"(a), "l"(b), "l"(c));
    return d;
}
__device__ __forceinline__ float lo_hi_sum(ull v) {
    float2 f = *(float2*)&v;
    return f.x + f.y;
}

// ---------------- smem / async helpers ----------------
__device__ __forceinline__ uint32_t smem_u32(const void* p) {
    uint32_t a;
    asm("{ .reg .u64 t; cvta.to.shared.u64 t, %1; cvt.u32.u64 %0, t; }" : "=r"(a) : "l"(p));
    return a;
}
__device__ __forceinline__ void mbar_init(uint32_t mbar, uint32_t cnt) {
    asm volatile("mbarrier.init.shared.b64 [%0], %1;" :: "r"(mbar), "r"(cnt) : "memory");
}
__device__ __forceinline__ void mbar_expect_tx(uint32_t mbar, uint32_t bytes) {
    asm volatile("mbarrier.arrive.expect_tx.shared.b64 _, [%0], %1;" :: "r"(mbar), "r"(bytes) : "memory");
}
__device__ __forceinline__ void mbar_wait(uint32_t mbar, uint32_t phase) {
    asm volatile(
        "{\n\t.reg .pred P;\n"
        "WL_%=:\n\t"
        "mbarrier.try_wait.parity.shared.b64 P, [%0], %1;\n\t"
        "@!P bra WL_%=;\n\t}"
        :: "r"(mbar), "r"(phase) : "memory");
}
__device__ __forceinline__ void bulk_cp(uint32_t dst_smem, const void* src, uint32_t bytes, uint32_t mbar) {
    asm volatile(
        "cp.async.bulk.shared::cluster.global.mbarrier::complete_tx::bytes [%0], [%1], %2, [%3];"
        :: "r"(dst_smem), "l"(src), "r"(bytes), "r"(mbar) : "memory");
}
__device__ __forceinline__ void cp_async16(uint32_t dst, const void* src, uint32_t srcbytes) {
    asm volatile("cp.async.ca.shared.global [%0], [%1], 16, %2;"
                 :: "r"(dst), "l"(src), "r"(srcbytes) : "memory");
}
#define CP_COMMIT() asm volatile("cp.async.commit_group;" ::: "memory")
#define CP_WAIT1()  asm volatile("cp.async.wait_group 1;" ::: "memory")
#define CP_WAIT0()  asm volatile("cp.async.wait_group 0;" ::: "memory")

// =============================================================================
// Kernel 1: x_proj GEMM (unchanged from R7 — 2-stage cp.async, f32x2 K-paired)
// =============================================================================
__global__ void __launch_bounds__(256) k_xproj(
    const float* __restrict__ emb,
    const float* __restrict__ Wf, const float* __restrict__ bf,
    const float* __restrict__ Wb, const float* __restrict__ bb,
    const int*   __restrict__ sent)
{
    __shared__ float As[2][64 * 32];
    __shared__ float Bs[2][64 * 32];
    __shared__ int   ws[64];

    int t   = blockIdx.y;
    int n0  = blockIdx.x * 64;
    int dir = (n0 >= 1024) ? 1 : 0;
    const float* W    = dir ? Wb : Wf;
    const float* bias = dir ? bb : bf;
    int gbase = n0 & 1023;
    int tid = threadIdx.x;

    if (tid < 64) ws[tid] = sent[t * 64 + tid];
    __syncthreads();

    uint32_t as_base = smem_u32(&As[0][0]);
    uint32_t bs_base = smem_u32(&Bs[0][0]);

    int r0 = tid >> 3,          sl0 = tid & 7;
    int r1 = (tid + 256) >> 3,  sl1 = (tid + 256) & 7;
    uint32_t d0 = (uint32_t)(r0 * 128 + ((sl0 ^ (r0 & 7)) << 4));
    uint32_t d1 = (uint32_t)(r1 * 128 + ((sl1 ^ (r1 & 7)) << 4));
    const float* arow0 = emb + (size_t)ws[r0] * EMB;
    const float* arow1 = emb + (size_t)ws[r1] * EMB;
    const float* brow0 = W + (size_t)(gbase + r0) * EMB;
    const float* brow1 = W + (size_t)(gbase + r1) * EMB;

    auto issue = [&](int kt, int buf) {
        int k0 = kt * 32;
        uint32_t boff = (uint32_t)(buf * 8192);
        int kg0 = k0 + sl0 * 4, kg1 = k0 + sl1 * 4;
        uint32_t n0b = (kg0 + 4 <= EMB) ? 16u : 0u;
        uint32_t n1b = (kg1 + 4 <= EMB) ? 16u : 0u;
        cp_async16(as_base + boff + d0, arow0 + (n0b ? kg0 : 0), n0b);
        cp_async16(as_base + boff + d1, arow1 + (n1b ? kg1 : 0), n1b);
        cp_async16(bs_base + boff + d0, brow0 + (n0b ? kg0 : 0), n0b);
        cp_async16(bs_base + boff + d1, brow1 + (n1b ? kg1 : 0), n1b);
    };

    ull acc[4][4];
    #pragma unroll
    for (int i = 0; i < 4; i++)
        #pragma unroll
        for (int j = 0; j < 4; j++) acc[i][j] = 0ull;

    int tx = tid & 15;
    int ty = tid >> 4;
    int sa = tx & 7;
    int sb = ty & 7;

    issue(0, 0);
    CP_COMMIT();

    for (int kt = 0; kt < 10; kt++) {
        if (kt < 9) {
            issue(kt + 1, (kt + 1) & 1);
            CP_COMMIT();
            CP_WAIT1();
        } else {
            CP_WAIT0();
        }
        __syncthreads();

        const float* Ab = &As[kt & 1][0];
        const float* Bb = &Bs[kt & 1][0];
        #pragma unroll
        for (int c = 0; c < 8; c++) {
            ulonglong2 a[4], b[4];
            int ca = (c ^ sa) << 2;
            int cb = (c ^ sb) << 2;
            #pragma unroll
            for (int i = 0; i < 4; i++)
                a[i] = *(const ulonglong2*)&Ab[(tx + 16 * i) * 32 + ca];
            #pragma unroll
            for (int j = 0; j < 4; j++)
                b[j] = *(const ulonglong2*)&Bb[(ty + 16 * j) * 32 + cb];
            #pragma unroll
            for (int i = 0; i < 4; i++)
                #pragma unroll
                for (int j = 0; j < 4; j++) {
                    acc[i][j] = ffma2(a[i].x, b[j].x, acc[i][j]);
                    acc[i][j] = ffma2(a[i].y, b[j].y, acc[i][j]);
                }
        }
        __syncthreads();
    }

    #pragma unroll
    for (int j = 0; j < 4; j++) {
        int g = gbase + ty + 16 * j;
        float bv = bias[g];
        #pragma unroll
        for (int i = 0; i < 4; i++) {
            int m = tx + 16 * i;
            g_xproj[dir][t][g][m] = lo_hi_sum(acc[i][j]) + bv;
        }
    }
}

// =============================================================================
// Kernel 2: persistent bidirectional LSTM — REWRITTEN inner loop.
// warp = k-slice (32 k's, waits only its own TMA chunk); lane = (gq:4, bq:8):
// 4 gate-types x 8 batches per thread. Loads are broadcast-friendly LDS.128:
// crossbar ~1.3k cyc/step (was ~12k). Cross-warp k-reduce via 32KB smem.
// =============================================================================
__device__ __forceinline__ float sigf(float x) { return 1.f / (1.f + __expf(-x)); }

__device__ __forceinline__ void grid_barrier2(int bx, int tid, unsigned target)
{
    __threadfence();
    __syncthreads();
    if (tid == 0) ((volatile unsigned*)g_flags)[bx] = target;
    if (bx == 0) {
        if (tid < 32) {
            volatile unsigned* f = g_flags;
            for (;;) {
                bool ok = (f[tid] >= target) & (f[tid + 32] >= target)
                        & (f[tid + 64] >= target) & (f[tid + 96] >= target);
                if (__all_sync(0xffffffffu, ok)) break;
            }
            if (tid == 0) {
                __threadfence();
                *(volatile unsigned*)&g_rel = target;
            }
        }
    } else if (tid == 0) {
        volatile unsigned* r = &g_rel;
        while (*r < target) {}
    }
    __syncthreads();
    __threadfence();
}

// smem: Ws2 32KB | hs 64KB | red 32KB | mbars
#define LSTM_SMEM (32768 + 65536 + 32768 + 64)

__global__ void __launch_bounds__(256) k_lstm(
    const float* __restrict__ Whf, const float* __restrict__ Whb)
{
    extern __shared__ float sm[];
    ull*   Ws2 = (ull*)sm;                  // [k=256][16 gates] dup-pairs, 32KB
    float* hs  = sm + 8192;                 // [k=256][b=64], 64KB
    float* red = sm + 8192 + 16384;         // [ks=8][gi=16][b=64], 32KB
    uint32_t mbar0 = smem_u32(sm + 32768);  // 4 mbarriers

    int bx  = blockIdx.x;
    int dir = bx >> 6;
    int cc  = bx & 63;
    const float* Whh = dir ? Whb : Whf;
    int tid = threadIdx.x;

    // preload duplicated Whh slice: Ws2[k*16 + (q*4+j)] = dup(Whh[q*256+4cc+j][k])
    for (int idx = tid; idx < 4096; idx += 256) {
        int k = idx & 255, r = idx >> 8;
        int q = r >> 2, j = r & 3;
        float w = Whh[(q * 256 + 4 * cc + j) * HID + k];
        float2 w2 = make_float2(w, w);
        Ws2[k * 16 + r] = *(ull*)&w2;
    }
    if (tid == 0)
        for (int ch = 0; ch < 4; ch++) mbar_init(mbar0 + ch * 8, 1);
    __syncthreads();

    int lane = tid & 31;
    int ks   = tid >> 5;        // warp id = k-slice (32 k each)
    int gq   = lane >> 3;       // gate type 0..3 (i,f,g,o)
    int bq   = lane & 7;        // batch octet 0..7
    int kbase = ks * 32;
    uint32_t my_mbar = mbar0 + (ks >> 1) * 8;   // chunk = 64 k

    int jrow = tid >> 6;        // activation: hid col offset 0..3
    int bcol = tid & 63;        // activation: batch
    float cstate = 0.f;

    float* hb = &g_h[dir][0][0][0];
    uint32_t hs_smem = smem_u32(hs);

    for (int step = 0; step < T; step++) {
        int t = dir ? (T - 1 - step) : step;

        if (step > 0 && tid == 0) {
            int tprev = dir ? (t + 1) : (t - 1);
            const float* src = hb + tprev * HID * Bt;
            #pragma unroll
            for (int ch = 0; ch < 4; ch++) {
                mbar_expect_tx(mbar0 + ch * 8, 16384);
                bulk_cp(hs_smem + ch * 16384, src + ch * 4096, 16384, mbar0 + ch * 8);
            }
        }

        // prefetch x_proj for the activation phase (this thread's (jrow,bcol))
        float xp[4];
        #pragma unroll
        for (int q2 = 0; q2 < 4; q2++)
            xp[q2] = g_xproj[dir][t][q2 * 256 + 4 * cc + jrow][bcol];

        // ---- gate GEMM partials: acc[j][p] over this warp's 32 k's ----
        ull acc[4][4];
        #pragma unroll
        for (int j = 0; j < 4; j++)
            #pragma unroll
            for (int p = 0; p < 4; p++) acc[j][p] = 0ull;

        if (step > 0) {
            uint32_t phase = (unsigned)(step - 1) & 1u;
            mbar_wait(my_mbar, phase);   // each warp waits only its own chunk
            #pragma unroll 8
            for (int kk = 0; kk < 32; kk++) {
                int k = kbase + kk;
                const ull* wrow = Ws2 + k * 16 + gq * 4;
                ulonglong2 wv0 = *(const ulonglong2*)wrow;         // w for j=0,1
                ulonglong2 wv1 = *(const ulonglong2*)(wrow + 2);   // w for j=2,3
                const float* hrow = hs + k * 64 + bq * 8;
                ulonglong2 ha = *(const ulonglong2*)hrow;          // b pairs 0,1
                ulonglong2 hb2 = *(const ulonglong2*)(hrow + 4);   // b pairs 2,3
                acc[0][0] = ffma2(wv0.x, ha.x,  acc[0][0]);
                acc[0][1] = ffma2(wv0.x, ha.y,  acc[0][1]);
                acc[0][2] = ffma2(wv0.x, hb2.x, acc[0][2]);
                acc[0][3] = ffma2(wv0.x, hb2.y, acc[0][3]);
                acc[1][0] = ffma2(wv0.y, ha.x,  acc[1][0]);
                acc[1][1] = ffma2(wv0.y, ha.y,  acc[1][1]);
                acc[1][2] = ffma2(wv0.y, hb2.x, acc[1][2]);
                acc[1][3] = ffma2(wv0.y, hb2.y, acc[1][3]);
                acc[2][0] = ffma2(wv1.x, ha.x,  acc[2][0]);
                acc[2][1] = ffma2(wv1.x, ha.y,  acc[2][1]);
                acc[2][2] = ffma2(wv1.x, hb2.x, acc[2][2]);
                acc[2][3] = ffma2(wv1.x, hb2.y, acc[2][3]);
                acc[3][0] = ffma2(wv1.y, ha.x,  acc[3][0]);
                acc[3][1] = ffma2(wv1.y, ha.y,  acc[3][1]);
                acc[3][2] = ffma2(wv1.y, hb2.x, acc[3][2]);
                acc[3][3] = ffma2(wv1.y, hb2.y, acc[3][3]);
            }
        }

        // ---- store partials: red[ks][gq*4+j][bq*8 .. +8] ----
        {
            float* rrow = red + (ks * 16 + gq * 4) * 64 + bq * 8;
            #pragma unroll
            for (int j = 0; j < 4; j++) {
                ulonglong2 v0; v0.x = acc[j][0]; v0.y = acc[j][1];
                ulonglong2 v1; v1.x = acc[j][2]; v1.y = acc[j][3];
                *(ulonglong2*)(rrow + j * 64)     = v0;
                *(ulonglong2*)(rrow + j * 64 + 4) = v1;
            }
        }
        __syncthreads();

        // ---- reduce over ks + activations: thread -> (hid 4cc+jrow, batch bcol)
        float iv = xp[0], fv = xp[1], gv = xp[2], ov = xp[3];
        #pragma unroll
        for (int s = 0; s < 8; s++) {
            iv += red[(s * 16 +  0 + jrow) * 64 + bcol];
            fv += red[(s * 16 +  4 + jrow) * 64 + bcol];
            gv += red[(s * 16 +  8 + jrow) * 64 + bcol];
            ov += red[(s * 16 + 12 + jrow) * 64 + bcol];
        }
        cstate = sigf(fv) * cstate + sigf(iv) * tanhf(gv);
        float hv = sigf(ov) * tanhf(cstate);
        hb[t * HID * Bt + (4 * cc + jrow) * Bt + bcol] = hv;

        grid_barrier2(bx, tid, (unsigned)(step + 1));
    }
}

// =============================================================================
// Kernel 3: emissions
// =============================================================================
__global__ void __launch_bounds__(256) k_emis(
    const float* __restrict__ Wt, const float* __restrict__ bt)
{
    extern __shared__ float sm[];
    float* Wts = sm;
    float* hch = sm + 10240;

    int t = blockIdx.x, tid = threadIdx.x;
    for (int i = tid; i < NLAB * 2 * HID; i += 256) Wts[i] = Wt[i];

    float acc[5] = {0.f, 0.f, 0.f, 0.f, 0.f};
    int b = tid & 63;
    int lbase = tid >> 6;

    for (int d = 0; d < 2; d++) {
        const float* hsrc = &g_h[d][t][0][0];
        for (int jc = 0; jc < 4; jc++) {
            __syncthreads();
            for (int i = tid; i < 4096; i += 256) hch[i] = hsrc[jc * 4096 + i];
            __syncthreads();
            #pragma unroll 4
            for (int j2 = 0; j2 < 64; j2++) {
                float hv = hch[j2 * 64 + b];
                #pragma unroll
                for (int s = 0; s < 5; s++) {
                    int l = lbase + 4 * s;
                    acc[s] += hv * Wts[l * 2 * HID + d * HID + jc * 64 + j2];
                }
            }
        }
    }
    #pragma unroll
    for (int s = 0; s < 5; s++) {
        int l = lbase + 4 * s;
        g_em[t][b][l] = acc[s] + bt[l];
    }
}

// =============================================================================
// Kernel 4: CRF per batch
// =============================================================================
__global__ void __launch_bounds__(64) k_crf(
    const int* __restrict__ sent, const int* __restrict__ labels,
    const float* __restrict__ start_t, const float* __restrict__ end_t,
    const float* __restrict__ trans)
{
    int b = blockIdx.x;
    int tid = threadIdx.x;
    __shared__ float s_score, s_denom;

    if (tid < 32) {
        int j = tid;
        float tcol[NLAB];
        #pragma unroll
        for (int i = 0; i < NLAB; i++) tcol[i] = (j < NLAB) ? trans[i * NLAB + j] : 0.f;
        float alpha = (j < NLAB) ? (start_t[j] + g_em[0][b][j]) : -1e30f;

        for (int t = 1; t < T; t++) {
            bool m = (sent[t * 64 + b] != 0);
            float em = (j < NLAB) ? g_em[t][b][j] : 0.f;
            float s[NLAB], mx = -1e30f;
            #pragma unroll
            for (int i = 0; i < NLAB; i++) {
                float ai = __shfl_sync(0xffffffffu, alpha, i);
                s[i] = ai + tcol[i];
                mx = fmaxf(mx, s[i]);
            }
            float sum = 0.f;
            #pragma unroll
            for (int i = 0; i < NLAB; i++) sum += __expf(s[i] - mx);
            float nxt = em + mx + __logf(sum);
            if (j < NLAB && m) alpha = nxt;
        }
        float v = (j < NLAB) ? (alpha + end_t[j]) : -1e30f;
        float mx = v;
        #pragma unroll
        for (int o = 16; o > 0; o >>= 1) mx = fmaxf(mx, __shfl_xor_sync(0xffffffffu, mx, o));
        float e = (j < NLAB) ? __expf(v - mx) : 0.f;
        #pragma unroll
        for (int o = 16; o > 0; o >>= 1) e += __shfl_xor_sync(0xffffffffu, e, o);
        if (tid == 0) s_denom = mx + __logf(e);
    } else {
        int l = tid - 32;
        float part = 0.f; int cnt = 0;
        for (int t = l; t < T; t += 32) {
            bool m = (sent[t * 64 + b] != 0);
            cnt += m ? 1 : 0;
            if (t >= 1 && m) {
                int tp = labels[(t - 1) * 64 + b];
                int tc = labels[t * 64 + b];
                part += trans[tp * NLAB + tc] + g_em[t][b][tc];
            }
        }
        #pragma unroll
        for (int o = 16; o > 0; o >>= 1) {
            part += __shfl_xor_sync(0xffffffffu, part, o);
            cnt  += __shfl_xor_sync(0xffffffffu, cnt, o);
        }
        if (l == 0) {
            int tag0 = labels[b];
            float score = start_t[tag0] + g_em[0][b][tag0] + part;
            int se = cnt - 1;
            int last = labels[se * 64 + b];
            score += end_t[last];
            s_score = score;
        }
    }
    __syncthreads();
    if (tid == 0) g_part[b] = s_denom - s_score;
}

__global__ void k_reduce(float* out)
{
    if (threadIdx.x == 0) {
        float s = 0.f;
        for (int b = 0; b < Bt; b++) s += g_part[b];
        out[0] = s;
    }
}

__global__ void k_reset()
{
    int i = threadIdx.x;
    if (i < 128) g_flags[i] = 0u;
    if (i == 0)  g_rel = 0u;
}

// =============================================================================
extern "C" void kernel_launch(void* const* d_in, const int* in_sizes, int n_in,
                              void* d_out, int out_size)
{
    const float* emb    = (const float*)d_in[0];
    const float* Wih_f  = (const float*)d_in[1];
    const float* Whh_f  = (const float*)d_in[2];
    const float* b_f    = (const float*)d_in[3];
    const float* Wih_b  = (const float*)d_in[4];
    const float* Whh_b  = (const float*)d_in[5];
    const float* b_b    = (const float*)d_in[6];
    const float* W_top  = (const float*)d_in[7];
    const float* b_top  = (const float*)d_in[8];
    const float* startt = (const float*)d_in[9];
    const float* endt   = (const float*)d_in[10];
    const float* trans  = (const float*)d_in[11];
    const int*   sent   = (const int*)d_in[12];
    const int*   labels = (const int*)d_in[13];
    float* out = (float*)d_out;

    cudaFuncSetAttribute(k_lstm, cudaFuncAttributeMaxDynamicSharedMemorySize, LSTM_SMEM);
    cudaFuncSetAttribute(k_emis, cudaFuncAttributeMaxDynamicSharedMemorySize, 57344);

    k_reset<<<1, 128>>>();
    k_xproj<<<dim3(32, 256), 256>>>(emb, Wih_f, b_f, Wih_b, b_b, sent);
    k_lstm <<<128, 256, LSTM_SMEM>>>(Whh_f, Whh_b);
    k_emis <<<256, 256, 57344>>>(W_top, b_top);
    k_crf  <<<64, 64>>>(sent, labels, startt, endt, trans);
    k_reduce<<<1, 32>>>(out);
}